// round 16
// baseline (speedup 1.0000x reference)
#include <cuda_runtime.h>
#include <cuda_fp16.h>
#include <math.h>
#include <stdint.h>

#define EMBED 2048
#define SEQ   2048
#define NHEAD 16
#define DHEAD 128
#define BATCH 2
#define MTOT  (BATCH*SEQ)   // 4096

// ---------------- static device scratch (fp16) ----------------
__device__ __half g_xh[MTOT*EMBED];
__device__ __half g_Wh[4*EMBED*EMBED];
__device__ __half g_ch[MTOT*EMBED];
__device__ __half g_Qh[BATCH*NHEAD*SEQ*DHEAD];
__device__ __half g_Kh[BATCH*NHEAD*SEQ*DHEAD];
__device__ __half g_Vh[BATCH*NHEAD*SEQ*DHEAD];
__device__ float g_rsin[SEQ*64];
__device__ float g_rcos[SEQ*64];

// ---------------- baseline-PTX helpers ----------------
__device__ __forceinline__ uint32_t smem_to_u32(const void* p) {
    uint32_t a;
    asm("{ .reg .u64 t; cvta.to.shared.u64 t, %1; cvt.u32.u64 %0, t; }" : "=r"(a) : "l"(p));
    return a;
}
#define CP_ASYNC16(saddr, gptr) \
    asm volatile("cp.async.cg.shared.global [%0], [%1], 16;" :: "r"(saddr), "l"(gptr) : "memory")
#define CP_COMMIT() asm volatile("cp.async.commit_group;" ::: "memory")
#define CP_WAIT1()  asm volatile("cp.async.wait_group 1;" ::: "memory")
#define CP_WAIT3()  asm volatile("cp.async.wait_group 3;" ::: "memory")
#define CP_WAIT0()  asm volatile("cp.async.wait_group 0;" ::: "memory")

__device__ __forceinline__ void ldsm_x4(uint32_t* r, uint32_t addr) {
    asm volatile("ldmatrix.sync.aligned.m8n8.x4.shared.b16 {%0,%1,%2,%3}, [%4];"
                 : "=r"(r[0]), "=r"(r[1]), "=r"(r[2]), "=r"(r[3]) : "r"(addr));
}
__device__ __forceinline__ void ldsm_x4_t(uint32_t* r, uint32_t addr) {
    asm volatile("ldmatrix.sync.aligned.m8n8.x4.trans.shared.b16 {%0,%1,%2,%3}, [%4];"
                 : "=r"(r[0]), "=r"(r[1]), "=r"(r[2]), "=r"(r[3]) : "r"(addr));
}
__device__ __forceinline__ void mma_f16(float* c, const uint32_t* a, const uint32_t* b) {
    asm volatile("mma.sync.aligned.m16n8k16.row.col.f32.f16.f16.f32 "
                 "{%0,%1,%2,%3}, {%4,%5,%6,%7}, {%8,%9}, {%0,%1,%2,%3};"
                 : "+f"(c[0]), "+f"(c[1]), "+f"(c[2]), "+f"(c[3])
                 : "r"(a[0]), "r"(a[1]), "r"(a[2]), "r"(a[3]), "r"(b[0]), "r"(b[1]));
}
__device__ __forceinline__ uint32_t pack_h(float x, float y) {
    return ((uint32_t)__half_as_ushort(__float2half_rn(y)) << 16)
         | __half_as_ushort(__float2half_rn(x));
}

// ---------------- splits: f32 -> fp16 ----------------
__global__ void __launch_bounds__(256) split_x(const float* __restrict__ src, int n4)
{
    int idx = blockIdx.x * 256 + threadIdx.x;
    if (idx >= n4) return;
    float4 v = ((const float4*)src)[idx];
    *(uint2*)((uint32_t*)g_xh + idx*2) = make_uint2(pack_h(v.x, v.y), pack_h(v.z, v.w));
}

__global__ void __launch_bounds__(256) split_w(const float* __restrict__ w0,
                                               const float* __restrict__ w1,
                                               const float* __restrict__ w2,
                                               const float* __restrict__ w3, int n4)
{
    int idx = blockIdx.x * 256 + threadIdx.x;
    if (idx >= n4) return;
    const float* srcs[4] = {w0, w1, w2, w3};
    const float* src = srcs[blockIdx.y];
    float4 v = ((const float4*)src)[idx];
    __half* hi = g_Wh + (size_t)blockIdx.y * EMBED * EMBED;
    *(uint2*)((uint32_t*)hi + idx*2) = make_uint2(pack_h(v.x, v.y), pack_h(v.z, v.w));
}

// ---------------- RoPE table ----------------
__global__ void __launch_bounds__(256) rope_table()
{
    int idx = blockIdx.x * 256 + threadIdx.x;
    int i = idx & 63, s = idx >> 6;
    float freq = (float)pow(10000.0, -(double)i / 64.0);
    float ang  = (float)s * freq;
    double sn, cs;
    sincos((double)ang, &sn, &cs);
    g_rsin[idx] = (float)sn;
    g_rcos[idx] = (float)cs;
}

// ---------------- mma.sync fp16 GEMM v3: 8 warps (64x32), 4-stage pipeline -----
// mode = mode_base + blockIdx.z.
// mode 0: x->g_Qh (RoPE)  mode 1: x->g_Kh (RoPE)  mode 2: x->g_Vh  mode 3: ctx->Cout
#define GT_PITCH 80
#define GT_TILE  (128*GT_PITCH)      // 10240
#define GT_STAGE (2*GT_TILE)         // 20480
#define NSTAGE   4
#define CS_PITCH 134                 // 128*134*4 = 68608 <= NSTAGE*GT_STAGE
#define GEMM_SMEM (NSTAGE*GT_STAGE)  // 81920

__global__ void __launch_bounds__(256) gemm_mma(float* __restrict__ Cout, int mode_base)
{
    extern __shared__ char smc[];
    const uint32_t sbase = smem_to_u32(smc);
    const int tid  = threadIdx.x;
    const int lane = tid & 31;
    const int wid  = tid >> 5;
    const int warp_m = wid >> 2;          // 0..1
    const int warp_n = wid & 3;           // 0..3
    const int n0 = blockIdx.x * 128;
    const int m0 = blockIdx.y * 128;
    const int mode = mode_base + blockIdx.z;

    const __half* srcs[2];
    srcs[0] = ((mode == 3) ? g_ch : g_xh);
    srcs[1] = g_Wh + (size_t)mode * EMBED * EMBED;
    const int base_row[2] = {m0, n0};

    const int seg = tid & 3;              // 16B chunk within 64B k-row
    const int lr0 = tid >> 2;             // 0..63
    const int lr1 = lr0 + 64;

    const uint32_t a_off = (uint32_t)((warp_m*64 + (lane & 15)) * GT_PITCH + (lane >> 4) * 16);
    const uint32_t b_off = (uint32_t)(((lane & 7) + (lane >> 4) * 8 + warp_n*32) * GT_PITCH
                                      + ((lane >> 3) & 1) * 16);

    float acc[4][4][4];
    #pragma unroll
    for (int i = 0; i < 4; i++)
        #pragma unroll
        for (int j = 0; j < 4; j++)
            #pragma unroll
            for (int r = 0; r < 4; r++) acc[i][j][r] = 0.f;

    // ---- prefetch stages 0..2 ----
    #pragma unroll
    for (int ps = 0; ps < NSTAGE - 1; ps++) {
        const uint32_t sb = sbase + ps * GT_STAGE;
        const int k0 = ps * 32;
        #pragma unroll
        for (int t = 0; t < 2; t++) {
            CP_ASYNC16(sb + t*GT_TILE + lr0*GT_PITCH + seg*16,
                       srcs[t] + (size_t)(base_row[t] + lr0) * EMBED + k0 + seg*8);
            CP_ASYNC16(sb + t*GT_TILE + lr1*GT_PITCH + seg*16,
                       srcs[t] + (size_t)(base_row[t] + lr1) * EMBED + k0 + seg*8);
        }
        CP_COMMIT();
    }

    for (int s = 0; s < EMBED/32; s++) {
        if (s + NSTAGE - 1 < EMBED/32) {
            const uint32_t sb = sbase + ((s + NSTAGE - 1) % NSTAGE) * GT_STAGE;
            const int k0 = (s + NSTAGE - 1) * 32;
            #pragma unroll
            for (int t = 0; t < 2; t++) {
                CP_ASYNC16(sb + t*GT_TILE + lr0*GT_PITCH + seg*16,
                           srcs[t] + (size_t)(base_row[t] + lr0) * EMBED + k0 + seg*8);
                CP_ASYNC16(sb + t*GT_TILE + lr1*GT_PITCH + seg*16,
                           srcs[t] + (size_t)(base_row[t] + lr1) * EMBED + k0 + seg*8);
            }
        }
        CP_COMMIT();
        CP_WAIT3();           // stage s complete (3 newer groups may be pending)
        __syncthreads();

        const uint32_t sb = sbase + (s % NSTAGE) * GT_STAGE;
        #pragma unroll
        for (int kk = 0; kk < 2; kk++) {
            const uint32_t ko = kk * 32;
            uint32_t Af[4][4], Bf[2][4];
            #pragma unroll
            for (int ma = 0; ma < 4; ma++)
                ldsm_x4(Af[ma], sb + 0*GT_TILE + a_off + ko + ma*16*GT_PITCH);
            #pragma unroll
            for (int nb = 0; nb < 2; nb++)
                ldsm_x4(Bf[nb], sb + 1*GT_TILE + b_off + ko + nb*16*GT_PITCH);
            #pragma unroll
            for (int ma = 0; ma < 4; ma++)
                #pragma unroll
                for (int na = 0; na < 4; na++)
                    mma_f16(acc[ma][na], Af[ma], &Bf[na >> 1][(na & 1) * 2]);
        }
        __syncthreads();
    }

    const int r0 = lane >> 2;
    const int c0 = (lane & 3) * 2;

    if (mode <= 1) {
        // ---- fused RoPE epilogue: acc -> smem fp32 -> rotate -> fp16 hi ----
        float* Cs = (float*)smc;
        #pragma unroll
        for (int ma = 0; ma < 4; ma++)
            #pragma unroll
            for (int na = 0; na < 4; na++)
                #pragma unroll
                for (int half = 0; half < 2; half++) {
                    int rl = warp_m*64 + ma*16 + r0 + half*8;
                    int cl = warp_n*32 + na*8 + c0;
                    Cs[rl*CS_PITCH + cl]     = acc[ma][na][half*2];
                    Cs[rl*CS_PITCH + cl + 1] = acc[ma][na][half*2+1];
                }
        __syncthreads();

        __half* Hdst = (mode == 0) ? g_Qh : g_Kh;
        #pragma unroll
        for (int pass = 0; pass < 2; pass++) {
            const int r = pass*64 + (tid >> 2);
            const int m = m0 + r;
            const int bb = m >> 11, sq = m & (SEQ - 1);
            const size_t dst = ((size_t)((bb*NHEAD + blockIdx.x)*SEQ + sq))*DHEAD;
            const int g0 = (tid & 3) * 16;
            #pragma unroll
            for (int c = 0; c < 2; c++) {
                const int i0 = g0 + c*8;
                uint32_t hA[4], hB[4];
                #pragma unroll
                for (int j = 0; j < 4; j++) {
                    int i = i0 + 2*j;
                    float a0 = Cs[r*CS_PITCH + i],      a1 = Cs[r*CS_PITCH + i + 1];
                    float b0 = Cs[r*CS_PITCH + i + 64], b1 = Cs[r*CS_PITCH + i + 65];
                    float sn0 = g_rsin[sq*64 + i], sn1 = g_rsin[sq*64 + i + 1];
                    float cc0 = g_rcos[sq*64 + i], cc1 = g_rcos[sq*64 + i + 1];
                    hA[j] = pack_h(a0*cc0 - b0*sn0, a1*cc1 - b1*sn1);
                    hB[j] = pack_h(b0*cc0 + a0*sn0, b1*cc1 + a1*sn1);
                }
                *(uint4*)(Hdst + dst + i0)      = make_uint4(hA[0], hA[1], hA[2], hA[3]);
                *(uint4*)(Hdst + dst + i0 + 64) = make_uint4(hB[0], hB[1], hB[2], hB[3]);
            }
        }
    } else if (mode == 2) {
        #pragma unroll
        for (int ma = 0; ma < 4; ma++)
            #pragma unroll
            for (int na = 0; na < 4; na++) {
                const int coln = warp_n*32 + na*8 + c0;
                #pragma unroll
                for (int half = 0; half < 2; half++) {
                    const int m = m0 + warp_m*64 + ma*16 + r0 + half*8;
                    const int bb = m >> 11, ss = m & (SEQ - 1);
                    size_t off = ((size_t)((bb*NHEAD + blockIdx.x)*SEQ + ss))*DHEAD + coln;
                    *(uint32_t*)(g_Vh + off) = pack_h(acc[ma][na][half*2], acc[ma][na][half*2+1]);
                }
            }
    } else {
        #pragma unroll
        for (int ma = 0; ma < 4; ma++)
            #pragma unroll
            for (int na = 0; na < 4; na++) {
                const int coln = warp_n*32 + na*8 + c0;
                #pragma unroll
                for (int half = 0; half < 2; half++) {
                    const int m = m0 + warp_m*64 + ma*16 + r0 + half*8;
                    *(float2*)(Cout + (size_t)m * EMBED + n0 + coln) =
                        make_float2(acc[ma][na][half*2], acc[ma][na][half*2+1]);
                }
            }
    }
}

// ---------------- FA2-style fp16 attention (validated R15, unchanged) ----------
#define AP2    272
#define ATILE  (64*AP2)
#define AST2   (2*ATILE)
#define ABIAS2 (2*AST2)
#define ATTN_SMEM (ABIAS2 + 512)

__device__ __forceinline__ void attn_pf(uint32_t sb_stage,
    const __half* Kh, const __half* Vh, int k0, int tid)
{
    #pragma unroll
    for (int i = 0; i < 4; i++) {
        int idx = tid + i*256;
        int r = idx >> 4, c = idx & 15;
        uint32_t so = sb_stage + r*AP2 + c*16;
        size_t go = (size_t)(k0 + r) * DHEAD;
        CP_ASYNC16(so,         (const char*)(Kh + go) + c*16);
        CP_ASYNC16(so + ATILE, (const char*)(Vh + go) + c*16);
    }
}

__global__ void __launch_bounds__(256) attn_mma(const float* __restrict__ mask)
{
    extern __shared__ char smc[];
    const uint32_t sb = smem_to_u32(smc);
    const int tid = threadIdx.x, lane = tid & 31, wid = tid >> 5;
    const int qt = gridDim.x - 1 - blockIdx.x;
    const int h = blockIdx.y, b = blockIdx.z;
    const int q0 = qt * 128;
    const size_t hb = (size_t)(b*NHEAD + h) * SEQ * DHEAD;
    const __half *Qhp = g_Qh + hb;
    const __half *Khp = g_Kh + hb, *Vhp = g_Vh + hb;
    float* bias_sm = (float*)(smc + ABIAS2);

    #pragma unroll
    for (int i = 0; i < 8; i++) {
        int idx = tid + i*256;
        int r = idx >> 4, c = idx & 15;
        size_t go = (size_t)(q0 + r) * DHEAD;
        CP_ASYNC16(sb + r*AP2 + c*16, (const char*)(Qhp + go) + c*16);
    }
    CP_COMMIT();
    CP_WAIT0();
    __syncthreads();

    const uint32_t qa_off = (uint32_t)((wid*16 + (lane & 15))*AP2 + (lane >> 4)*16);
    uint32_t Qf[8][4];
    #pragma unroll
    for (int t = 0; t < 8; t++) ldsm_x4(Qf[t], sb + qa_off + t*32);
    __syncthreads();

    attn_pf(sb, Khp, Vhp, 0, tid);
    if (tid < 64) bias_sm[tid] = (1.0f - mask[b*SEQ + tid]) * -1e9f;
    CP_COMMIT();

    float O[16][4];
    #pragma unroll
    for (int j = 0; j < 16; j++)
        #pragma unroll
        for (int r = 0; r < 4; r++) O[j][r] = 0.f;
    float m_a = -1e30f, m_b = -1e30f, l_a = 0.f, l_b = 0.f;
    const float scale = 0.08838834764831845f;
    const int q_a = q0 + wid*16 + (lane >> 2);
    const int klo = 2*(lane & 3);
    const int nkt = 2*qt + 2;

    for (int kt = 0; kt < nkt; kt++) {
        const int stage = kt & 1;
        if (kt + 1 < nkt) {
            attn_pf(sb + (stage^1)*AST2, Khp, Vhp, (kt+1)*64, tid);
            if (tid < 64) bias_sm[(stage^1)*64 + tid] = (1.0f - mask[b*SEQ + (kt+1)*64 + tid]) * -1e9f;
        }
        CP_COMMIT();
        CP_WAIT1();
        __syncthreads();

        const uint32_t ss = sb + stage*AST2;
        float s[8][4];
        #pragma unroll
        for (int j = 0; j < 8; j++)
            #pragma unroll
            for (int r = 0; r < 4; r++) s[j][r] = 0.f;

        #pragma unroll
        for (int t = 0; t < 8; t++) {
            uint32_t Kh4[4][4];
            #pragma unroll
            for (int g = 0; g < 4; g++) {
                uint32_t Baddr = ss + (g*16 + (lane & 7) + ((lane >> 4) << 3))*AP2
                               + t*32 + ((lane >> 3) & 1)*16;
                ldsm_x4(Kh4[g], Baddr);
            }
            #pragma unroll
            for (int j = 0; j < 8; j++) mma_f16(s[j], Qf[t], &Kh4[j>>1][(j&1)*2]);
        }

        const float* bp = bias_sm + stage*64;
        const bool diag = (kt >= 2*qt);
        float tmax_a = -1e30f, tmax_b = -1e30f;
        #pragma unroll
        for (int j = 0; j < 8; j++) {
            int kk = 8*j + klo;
            float b0 = bp[kk], b1 = bp[kk+1];
            s[j][0] = s[j][0]*scale + b0;  s[j][1] = s[j][1]*scale + b1;
            s[j][2] = s[j][2]*scale + b0;  s[j][3] = s[j][3]*scale + b1;
            if (diag) {
                int kg = kt*64 + kk;
                if (kg   > q_a)   s[j][0] = -1e30f;
                if (kg+1 > q_a)   s[j][1] = -1e30f;
                if (kg   > q_a+8) s[j][2] = -1e30f;
                if (kg+1 > q_a+8) s[j][3] = -1e30f;
            }
            tmax_a = fmaxf(tmax_a, fmaxf(s[j][0], s[j][1]));
            tmax_b = fmaxf(tmax_b, fmaxf(s[j][2], s[j][3]));
        }
        tmax_a = fmaxf(tmax_a, __shfl_xor_sync(0xffffffffu, tmax_a, 1));
        tmax_a = fmaxf(tmax_a, __shfl_xor_sync(0xffffffffu, tmax_a, 2));
        tmax_b = fmaxf(tmax_b, __shfl_xor_sync(0xffffffffu, tmax_b, 1));
        tmax_b = fmaxf(tmax_b, __shfl_xor_sync(0xffffffffu, tmax_b, 2));
        float mn_a = fmaxf(m_a, tmax_a), mn_b = fmaxf(m_b, tmax_b);
        float ca = __expf(m_a - mn_a), cb = __expf(m_b - mn_b);
        m_a = mn_a; m_b = mn_b;
        float sum_a = 0.f, sum_b = 0.f;
        #pragma unroll
        for (int j = 0; j < 8; j++) {
            s[j][0] = __expf(s[j][0] - mn_a);  s[j][1] = __expf(s[j][1] - mn_a);
            s[j][2] = __expf(s[j][2] - mn_b);  s[j][3] = __expf(s[j][3] - mn_b);
            sum_a += s[j][0] + s[j][1];
            sum_b += s[j][2] + s[j][3];
        }
        sum_a += __shfl_xor_sync(0xffffffffu, sum_a, 1);
        sum_a += __shfl_xor_sync(0xffffffffu, sum_a, 2);
        sum_b += __shfl_xor_sync(0xffffffffu, sum_b, 1);
        sum_b += __shfl_xor_sync(0xffffffffu, sum_b, 2);
        l_a = l_a*ca + sum_a;
        l_b = l_b*cb + sum_b;
        #pragma unroll
        for (int j = 0; j < 16; j++) {
            O[j][0] *= ca; O[j][1] *= ca; O[j][2] *= cb; O[j][3] *= cb;
        }

        #pragma unroll
        for (int t = 0; t < 4; t++) {
            uint32_t aH[4];
            aH[0] = pack_h(s[2*t][0],   s[2*t][1]);
            aH[1] = pack_h(s[2*t][2],   s[2*t][3]);
            aH[2] = pack_h(s[2*t+1][0], s[2*t+1][1]);
            aH[3] = pack_h(s[2*t+1][2], s[2*t+1][3]);
            #pragma unroll
            for (int g = 0; g < 8; g++) {
                uint32_t Baddr = ss + ATILE
                               + (t*16 + (lane & 7) + ((lane >> 3) & 1)*8)*AP2
                               + g*32 + (lane >> 4)*16;
                uint32_t Vh4[4];
                ldsm_x4_t(Vh4, Baddr);
                mma_f16(O[2*g],   aH, Vh4);
                mma_f16(O[2*g+1], aH, Vh4+2);
            }
        }
        __syncthreads();
    }

    const float ia = 1.0f / l_a, ib = 1.0f / l_b;
    const size_t ra = (size_t)(b*SEQ + q0 + wid*16 + (lane >> 2));
    const size_t oa = ra*EMBED + h*DHEAD + klo;
    const size_t ob = oa + 8*(size_t)EMBED;
    #pragma unroll
    for (int j = 0; j < 16; j++) {
        *(uint32_t*)(g_ch + oa + 8*j) = pack_h(O[j][0]*ia, O[j][1]*ia);
        *(uint32_t*)(g_ch + ob + 8*j) = pack_h(O[j][2]*ib, O[j][3]*ib);
    }
}

// ---------------- launch ----------------
extern "C" void kernel_launch(void* const* d_in, const int* in_sizes, int n_in,
                              void* d_out, int out_size)
{
    (void)in_sizes; (void)n_in; (void)out_size;
    const float* x    = (const float*)d_in[0];
    const float* mask = (const float*)d_in[1];
    const float* Wq   = (const float*)d_in[2];
    const float* Wk   = (const float*)d_in[3];
    const float* Wv   = (const float*)d_in[4];
    const float* Wo   = (const float*)d_in[5];
    float* out        = (float*)d_out;

    cudaFuncSetAttribute(gemm_mma, cudaFuncAttributeMaxDynamicSharedMemorySize, GEMM_SMEM);
    cudaFuncSetAttribute(attn_mma, cudaFuncAttributeMaxDynamicSharedMemorySize, ATTN_SMEM);

    const int n4x = MTOT*EMBED/4;
    const int n4w = EMBED*EMBED/4;

    split_x<<<(n4x+255)/256, 256>>>(x, n4x);
    split_w<<<dim3((n4w+255)/256, 4), 256>>>(Wq, Wk, Wv, Wo, n4w);
    rope_table<<<(SEQ*64)/256, 256>>>();

    gemm_mma<<<dim3(EMBED/128, MTOT/128, 3), 256, GEMM_SMEM>>>(nullptr, 0);

    attn_mma<<<dim3(SEQ/128, NHEAD, BATCH), 256, ATTN_SMEM>>>(mask);

    gemm_mma<<<dim3(EMBED/128, MTOT/128, 1), 256, GEMM_SMEM>>>(out, 3);
}

// round 17
// speedup vs baseline: 1.0804x; 1.0804x over previous
#include <cuda_runtime.h>
#include <cuda_fp16.h>
#include <math.h>
#include <stdint.h>

#define EMBED 2048
#define SEQ   2048
#define NHEAD 16
#define DHEAD 128
#define BATCH 2
#define MTOT  (BATCH*SEQ)   // 4096

// ---------------- static device scratch (fp16) ----------------
__device__ __half g_xh[MTOT*EMBED];
__device__ __half g_Wh[4*EMBED*EMBED];
__device__ __half g_ch[MTOT*EMBED];
__device__ __half g_Qh[BATCH*NHEAD*SEQ*DHEAD];
__device__ __half g_Kh[BATCH*NHEAD*SEQ*DHEAD];
__device__ __half g_Vh[BATCH*NHEAD*SEQ*DHEAD];
__device__ float g_rsin[SEQ*64];
__device__ float g_rcos[SEQ*64];

// ---------------- baseline-PTX helpers ----------------
__device__ __forceinline__ uint32_t smem_to_u32(const void* p) {
    uint32_t a;
    asm("{ .reg .u64 t; cvta.to.shared.u64 t, %1; cvt.u32.u64 %0, t; }" : "=r"(a) : "l"(p));
    return a;
}
#define CP_ASYNC16(saddr, gptr) \
    asm volatile("cp.async.cg.shared.global [%0], [%1], 16;" :: "r"(saddr), "l"(gptr) : "memory")
#define CP_COMMIT() asm volatile("cp.async.commit_group;" ::: "memory")
#define CP_WAIT1()  asm volatile("cp.async.wait_group 1;" ::: "memory")
#define CP_WAIT2()  asm volatile("cp.async.wait_group 2;" ::: "memory")
#define CP_WAIT0()  asm volatile("cp.async.wait_group 0;" ::: "memory")

__device__ __forceinline__ void ldsm_x4(uint32_t* r, uint32_t addr) {
    asm volatile("ldmatrix.sync.aligned.m8n8.x4.shared.b16 {%0,%1,%2,%3}, [%4];"
                 : "=r"(r[0]), "=r"(r[1]), "=r"(r[2]), "=r"(r[3]) : "r"(addr));
}
__device__ __forceinline__ void ldsm_x4_t(uint32_t* r, uint32_t addr) {
    asm volatile("ldmatrix.sync.aligned.m8n8.x4.trans.shared.b16 {%0,%1,%2,%3}, [%4];"
                 : "=r"(r[0]), "=r"(r[1]), "=r"(r[2]), "=r"(r[3]) : "r"(addr));
}
__device__ __forceinline__ void mma_f16(float* c, const uint32_t* a, const uint32_t* b) {
    asm volatile("mma.sync.aligned.m16n8k16.row.col.f32.f16.f16.f32 "
                 "{%0,%1,%2,%3}, {%4,%5,%6,%7}, {%8,%9}, {%0,%1,%2,%3};"
                 : "+f"(c[0]), "+f"(c[1]), "+f"(c[2]), "+f"(c[3])
                 : "r"(a[0]), "r"(a[1]), "r"(a[2]), "r"(a[3]), "r"(b[0]), "r"(b[1]));
}
__device__ __forceinline__ uint32_t pack_h(float x, float y) {
    return ((uint32_t)__half_as_ushort(__float2half_rn(y)) << 16)
         | __half_as_ushort(__float2half_rn(x));
}

// ---------------- splits: f32 -> fp16 ----------------
__global__ void __launch_bounds__(256) split_x(const float* __restrict__ src, int n4)
{
    int idx = blockIdx.x * 256 + threadIdx.x;
    if (idx >= n4) return;
    float4 v = ((const float4*)src)[idx];
    *(uint2*)((uint32_t*)g_xh + idx*2) = make_uint2(pack_h(v.x, v.y), pack_h(v.z, v.w));
}

__global__ void __launch_bounds__(256) split_w(const float* __restrict__ w0,
                                               const float* __restrict__ w1,
                                               const float* __restrict__ w2,
                                               const float* __restrict__ w3, int n4)
{
    int idx = blockIdx.x * 256 + threadIdx.x;
    if (idx >= n4) return;
    const float* srcs[4] = {w0, w1, w2, w3};
    const float* src = srcs[blockIdx.y];
    float4 v = ((const float4*)src)[idx];
    __half* hi = g_Wh + (size_t)blockIdx.y * EMBED * EMBED;
    *(uint2*)((uint32_t*)hi + idx*2) = make_uint2(pack_h(v.x, v.y), pack_h(v.z, v.w));
}

// ---------------- RoPE table ----------------
__global__ void __launch_bounds__(256) rope_table()
{
    int idx = blockIdx.x * 256 + threadIdx.x;
    int i = idx & 63, s = idx >> 6;
    float freq = (float)pow(10000.0, -(double)i / 64.0);
    float ang  = (float)s * freq;
    double sn, cs;
    sincos((double)ang, &sn, &cs);
    g_rsin[idx] = (float)sn;
    g_rcos[idx] = (float)cs;
}

// ---------------- mma.sync fp16 GEMM (R15 shape: 4 warps 64x64), 3-stage -------
// mode = mode_base + blockIdx.z.
// mode 0: x->g_Qh (RoPE)  mode 1: x->g_Kh (RoPE)  mode 2: x->g_Vh  mode 3: ctx->Cout
#define GT_PITCH 80
#define GT_TILE  (128*GT_PITCH)      // 10240
#define GT_STAGE (2*GT_TILE)         // 20480
#define NSTAGE   3
#define CS_PITCH 134
#define GEMM_SMEM (128*CS_PITCH*4)   // 68608 >= NSTAGE*GT_STAGE (61440)

__global__ void __launch_bounds__(128) gemm_mma(float* __restrict__ Cout, int mode_base)
{
    extern __shared__ char smc[];
    const uint32_t sbase = smem_to_u32(smc);
    const int tid  = threadIdx.x;
    const int lane = tid & 31;
    const int wid  = tid >> 5;
    const int warp_m = wid >> 1;
    const int warp_n = wid & 1;
    const int n0 = blockIdx.x * 128;
    const int m0 = blockIdx.y * 128;
    const int mode = mode_base + blockIdx.z;

    const __half* srcs[2];
    srcs[0] = ((mode == 3) ? g_ch : g_xh);
    srcs[1] = g_Wh + (size_t)mode * EMBED * EMBED;
    const int base_row[2] = {m0, n0};

    const int seg = tid & 3;
    const int rb  = tid >> 2;

    const uint32_t a_off = (uint32_t)((warp_m*64 + (lane & 15)) * GT_PITCH + (lane >> 4) * 16);
    const uint32_t b_off = (uint32_t)(((lane & 7) + (lane >> 4) * 8 + warp_n*64) * GT_PITCH
                                      + ((lane >> 3) & 1) * 16);

    float acc[4][8][4];
    #pragma unroll
    for (int i = 0; i < 4; i++)
        #pragma unroll
        for (int j = 0; j < 8; j++)
            #pragma unroll
            for (int r = 0; r < 4; r++) acc[i][j][r] = 0.f;

    // ---- prefetch stages 0..1 ----
    #pragma unroll
    for (int ps = 0; ps < NSTAGE - 1; ps++) {
        const uint32_t sb = sbase + ps * GT_STAGE;
        const int k0 = ps * 32;
        #pragma unroll
        for (int t = 0; t < 2; t++)
            #pragma unroll
            for (int i = 0; i < 4; i++) {
                int row = rb + i*32;
                CP_ASYNC16(sb + t*GT_TILE + row*GT_PITCH + seg*16,
                           srcs[t] + (size_t)(base_row[t] + row) * EMBED + k0 + seg*8);
            }
        CP_COMMIT();
    }

    for (int s = 0; s < EMBED/32; s++) {
        if (s + NSTAGE - 1 < EMBED/32) {
            const uint32_t sb = sbase + ((s + NSTAGE - 1) % NSTAGE) * GT_STAGE;
            const int k0 = (s + NSTAGE - 1) * 32;
            #pragma unroll
            for (int t = 0; t < 2; t++)
                #pragma unroll
                for (int i = 0; i < 4; i++) {
                    int row = rb + i*32;
                    CP_ASYNC16(sb + t*GT_TILE + row*GT_PITCH + seg*16,
                               srcs[t] + (size_t)(base_row[t] + row) * EMBED + k0 + seg*8);
                }
        }
        CP_COMMIT();
        CP_WAIT2();           // stage s complete; up to 2 newer stages in flight
        __syncthreads();

        const uint32_t sb = sbase + (s % NSTAGE) * GT_STAGE;
        #pragma unroll
        for (int kk = 0; kk < 2; kk++) {
            const uint32_t ko = kk * 32;
            uint32_t Af[4][4], Bf[4][4];
            #pragma unroll
            for (int ma = 0; ma < 4; ma++)
                ldsm_x4(Af[ma], sb + 0*GT_TILE + a_off + ko + ma*16*GT_PITCH);
            #pragma unroll
            for (int g = 0; g < 4; g++)
                ldsm_x4(Bf[g], sb + 1*GT_TILE + b_off + ko + g*16*GT_PITCH);
            #pragma unroll
            for (int ma = 0; ma < 4; ma++)
                #pragma unroll
                for (int na = 0; na < 8; na++)
                    mma_f16(acc[ma][na], Af[ma], &Bf[na >> 1][(na & 1) * 2]);
        }
        __syncthreads();
    }

    const int r0 = lane >> 2;
    const int c0 = (lane & 3) * 2;

    if (mode <= 1) {
        // ---- fused RoPE epilogue: acc -> smem fp32 -> rotate -> fp16 hi ----
        float* Cs = (float*)smc;
        #pragma unroll
        for (int ma = 0; ma < 4; ma++)
            #pragma unroll
            for (int na = 0; na < 8; na++)
                #pragma unroll
                for (int half = 0; half < 2; half++) {
                    int rl = warp_m*64 + ma*16 + r0 + half*8;
                    int cl = warp_n*64 + na*8 + c0;
                    Cs[rl*CS_PITCH + cl]     = acc[ma][na][half*2];
                    Cs[rl*CS_PITCH + cl + 1] = acc[ma][na][half*2+1];
                }
        __syncthreads();

        __half* Hdst = (mode == 0) ? g_Qh : g_Kh;
        #pragma unroll
        for (int pass = 0; pass < 4; pass++) {
            const int r = pass*32 + (tid >> 2);
            const int m = m0 + r;
            const int bb = m >> 11, sq = m & (SEQ - 1);
            const size_t dst = ((size_t)((bb*NHEAD + blockIdx.x)*SEQ + sq))*DHEAD;
            const int g0 = (tid & 3) * 16;
            #pragma unroll
            for (int c = 0; c < 2; c++) {
                const int i0 = g0 + c*8;
                uint32_t hA[4], hB[4];
                #pragma unroll
                for (int j = 0; j < 4; j++) {
                    int i = i0 + 2*j;
                    float a0 = Cs[r*CS_PITCH + i],      a1 = Cs[r*CS_PITCH + i + 1];
                    float b0 = Cs[r*CS_PITCH + i + 64], b1 = Cs[r*CS_PITCH + i + 65];
                    float sn0 = g_rsin[sq*64 + i], sn1 = g_rsin[sq*64 + i + 1];
                    float cc0 = g_rcos[sq*64 + i], cc1 = g_rcos[sq*64 + i + 1];
                    hA[j] = pack_h(a0*cc0 - b0*sn0, a1*cc1 - b1*sn1);
                    hB[j] = pack_h(b0*cc0 + a0*sn0, b1*cc1 + a1*sn1);
                }
                *(uint4*)(Hdst + dst + i0)      = make_uint4(hA[0], hA[1], hA[2], hA[3]);
                *(uint4*)(Hdst + dst + i0 + 64) = make_uint4(hB[0], hB[1], hB[2], hB[3]);
            }
        }
    } else if (mode == 2) {
        #pragma unroll
        for (int ma = 0; ma < 4; ma++)
            #pragma unroll
            for (int na = 0; na < 8; na++) {
                const int coln = warp_n*64 + na*8 + c0;
                #pragma unroll
                for (int half = 0; half < 2; half++) {
                    const int m = m0 + warp_m*64 + ma*16 + r0 + half*8;
                    const int bb = m >> 11, ss = m & (SEQ - 1);
                    size_t off = ((size_t)((bb*NHEAD + blockIdx.x)*SEQ + ss))*DHEAD + coln;
                    *(uint32_t*)(g_Vh + off) = pack_h(acc[ma][na][half*2], acc[ma][na][half*2+1]);
                }
            }
    } else {
        #pragma unroll
        for (int ma = 0; ma < 4; ma++)
            #pragma unroll
            for (int na = 0; na < 8; na++) {
                const int coln = warp_n*64 + na*8 + c0;
                #pragma unroll
                for (int half = 0; half < 2; half++) {
                    const int m = m0 + warp_m*64 + ma*16 + r0 + half*8;
                    *(float2*)(Cout + (size_t)m * EMBED + n0 + coln) =
                        make_float2(acc[ma][na][half*2], acc[ma][na][half*2+1]);
                }
            }
    }
}

// ---------------- FA2-style fp16 attention (validated R15, unchanged) ----------
#define AP2    272
#define ATILE  (64*AP2)
#define AST2   (2*ATILE)
#define ABIAS2 (2*AST2)
#define ATTN_SMEM (ABIAS2 + 512)

__device__ __forceinline__ void attn_pf(uint32_t sb_stage,
    const __half* Kh, const __half* Vh, int k0, int tid)
{
    #pragma unroll
    for (int i = 0; i < 4; i++) {
        int idx = tid + i*256;
        int r = idx >> 4, c = idx & 15;
        uint32_t so = sb_stage + r*AP2 + c*16;
        size_t go = (size_t)(k0 + r) * DHEAD;
        CP_ASYNC16(so,         (const char*)(Kh + go) + c*16);
        CP_ASYNC16(so + ATILE, (const char*)(Vh + go) + c*16);
    }
}

__global__ void __launch_bounds__(256) attn_mma(const float* __restrict__ mask)
{
    extern __shared__ char smc[];
    const uint32_t sb = smem_to_u32(smc);
    const int tid = threadIdx.x, lane = tid & 31, wid = tid >> 5;
    const int qt = gridDim.x - 1 - blockIdx.x;
    const int h = blockIdx.y, b = blockIdx.z;
    const int q0 = qt * 128;
    const size_t hb = (size_t)(b*NHEAD + h) * SEQ * DHEAD;
    const __half *Qhp = g_Qh + hb;
    const __half *Khp = g_Kh + hb, *Vhp = g_Vh + hb;
    float* bias_sm = (float*)(smc + ABIAS2);

    #pragma unroll
    for (int i = 0; i < 8; i++) {
        int idx = tid + i*256;
        int r = idx >> 4, c = idx & 15;
        size_t go = (size_t)(q0 + r) * DHEAD;
        CP_ASYNC16(sb + r*AP2 + c*16, (const char*)(Qhp + go) + c*16);
    }
    CP_COMMIT();
    CP_WAIT0();
    __syncthreads();

    const uint32_t qa_off = (uint32_t)((wid*16 + (lane & 15))*AP2 + (lane >> 4)*16);
    uint32_t Qf[8][4];
    #pragma unroll
    for (int t = 0; t < 8; t++) ldsm_x4(Qf[t], sb + qa_off + t*32);
    __syncthreads();

    attn_pf(sb, Khp, Vhp, 0, tid);
    if (tid < 64) bias_sm[tid] = (1.0f - mask[b*SEQ + tid]) * -1e9f;
    CP_COMMIT();

    float O[16][4];
    #pragma unroll
    for (int j = 0; j < 16; j++)
        #pragma unroll
        for (int r = 0; r < 4; r++) O[j][r] = 0.f;
    float m_a = -1e30f, m_b = -1e30f, l_a = 0.f, l_b = 0.f;
    const float scale = 0.08838834764831845f;
    const int q_a = q0 + wid*16 + (lane >> 2);
    const int klo = 2*(lane & 3);
    const int nkt = 2*qt + 2;

    for (int kt = 0; kt < nkt; kt++) {
        const int stage = kt & 1;
        if (kt + 1 < nkt) {
            attn_pf(sb + (stage^1)*AST2, Khp, Vhp, (kt+1)*64, tid);
            if (tid < 64) bias_sm[(stage^1)*64 + tid] = (1.0f - mask[b*SEQ + (kt+1)*64 + tid]) * -1e9f;
        }
        CP_COMMIT();
        CP_WAIT1();
        __syncthreads();

        const uint32_t ss = sb + stage*AST2;
        float s[8][4];
        #pragma unroll
        for (int j = 0; j < 8; j++)
            #pragma unroll
            for (int r = 0; r < 4; r++) s[j][r] = 0.f;

        #pragma unroll
        for (int t = 0; t < 8; t++) {
            uint32_t Kh4[4][4];
            #pragma unroll
            for (int g = 0; g < 4; g++) {
                uint32_t Baddr = ss + (g*16 + (lane & 7) + ((lane >> 4) << 3))*AP2
                               + t*32 + ((lane >> 3) & 1)*16;
                ldsm_x4(Kh4[g], Baddr);
            }
            #pragma unroll
            for (int j = 0; j < 8; j++) mma_f16(s[j], Qf[t], &Kh4[j>>1][(j&1)*2]);
        }

        const float* bp = bias_sm + stage*64;
        const bool diag = (kt >= 2*qt);
        float tmax_a = -1e30f, tmax_b = -1e30f;
        #pragma unroll
        for (int j = 0; j < 8; j++) {
            int kk = 8*j + klo;
            float b0 = bp[kk], b1 = bp[kk+1];
            s[j][0] = s[j][0]*scale + b0;  s[j][1] = s[j][1]*scale + b1;
            s[j][2] = s[j][2]*scale + b0;  s[j][3] = s[j][3]*scale + b1;
            if (diag) {
                int kg = kt*64 + kk;
                if (kg   > q_a)   s[j][0] = -1e30f;
                if (kg+1 > q_a)   s[j][1] = -1e30f;
                if (kg   > q_a+8) s[j][2] = -1e30f;
                if (kg+1 > q_a+8) s[j][3] = -1e30f;
            }
            tmax_a = fmaxf(tmax_a, fmaxf(s[j][0], s[j][1]));
            tmax_b = fmaxf(tmax_b, fmaxf(s[j][2], s[j][3]));
        }
        tmax_a = fmaxf(tmax_a, __shfl_xor_sync(0xffffffffu, tmax_a, 1));
        tmax_a = fmaxf(tmax_a, __shfl_xor_sync(0xffffffffu, tmax_a, 2));
        tmax_b = fmaxf(tmax_b, __shfl_xor_sync(0xffffffffu, tmax_b, 1));
        tmax_b = fmaxf(tmax_b, __shfl_xor_sync(0xffffffffu, tmax_b, 2));
        float mn_a = fmaxf(m_a, tmax_a), mn_b = fmaxf(m_b, tmax_b);
        float ca = __expf(m_a - mn_a), cb = __expf(m_b - mn_b);
        m_a = mn_a; m_b = mn_b;
        float sum_a = 0.f, sum_b = 0.f;
        #pragma unroll
        for (int j = 0; j < 8; j++) {
            s[j][0] = __expf(s[j][0] - mn_a);  s[j][1] = __expf(s[j][1] - mn_a);
            s[j][2] = __expf(s[j][2] - mn_b);  s[j][3] = __expf(s[j][3] - mn_b);
            sum_a += s[j][0] + s[j][1];
            sum_b += s[j][2] + s[j][3];
        }
        sum_a += __shfl_xor_sync(0xffffffffu, sum_a, 1);
        sum_a += __shfl_xor_sync(0xffffffffu, sum_a, 2);
        sum_b += __shfl_xor_sync(0xffffffffu, sum_b, 1);
        sum_b += __shfl_xor_sync(0xffffffffu, sum_b, 2);
        l_a = l_a*ca + sum_a;
        l_b = l_b*cb + sum_b;
        #pragma unroll
        for (int j = 0; j < 16; j++) {
            O[j][0] *= ca; O[j][1] *= ca; O[j][2] *= cb; O[j][3] *= cb;
        }

        #pragma unroll
        for (int t = 0; t < 4; t++) {
            uint32_t aH[4];
            aH[0] = pack_h(s[2*t][0],   s[2*t][1]);
            aH[1] = pack_h(s[2*t][2],   s[2*t][3]);
            aH[2] = pack_h(s[2*t+1][0], s[2*t+1][1]);
            aH[3] = pack_h(s[2*t+1][2], s[2*t+1][3]);
            #pragma unroll
            for (int g = 0; g < 8; g++) {
                uint32_t Baddr = ss + ATILE
                               + (t*16 + (lane & 7) + ((lane >> 3) & 1)*8)*AP2
                               + g*32 + (lane >> 4)*16;
                uint32_t Vh4[4];
                ldsm_x4_t(Vh4, Baddr);
                mma_f16(O[2*g],   aH, Vh4);
                mma_f16(O[2*g+1], aH, Vh4+2);
            }
        }
        __syncthreads();
    }

    const float ia = 1.0f / l_a, ib = 1.0f / l_b;
    const size_t ra = (size_t)(b*SEQ + q0 + wid*16 + (lane >> 2));
    const size_t oa = ra*EMBED + h*DHEAD + klo;
    const size_t ob = oa + 8*(size_t)EMBED;
    #pragma unroll
    for (int j = 0; j < 16; j++) {
        *(uint32_t*)(g_ch + oa + 8*j) = pack_h(O[j][0]*ia, O[j][1]*ia);
        *(uint32_t*)(g_ch + ob + 8*j) = pack_h(O[j][2]*ib, O[j][3]*ib);
    }
}

// ---------------- launch ----------------
extern "C" void kernel_launch(void* const* d_in, const int* in_sizes, int n_in,
                              void* d_out, int out_size)
{
    (void)in_sizes; (void)n_in; (void)out_size;
    const float* x    = (const float*)d_in[0];
    const float* mask = (const float*)d_in[1];
    const float* Wq   = (const float*)d_in[2];
    const float* Wk   = (const float*)d_in[3];
    const float* Wv   = (const float*)d_in[4];
    const float* Wo   = (const float*)d_in[5];
    float* out        = (float*)d_out;

    cudaFuncSetAttribute(gemm_mma, cudaFuncAttributeMaxDynamicSharedMemorySize, GEMM_SMEM);
    cudaFuncSetAttribute(attn_mma, cudaFuncAttributeMaxDynamicSharedMemorySize, ATTN_SMEM);

    const int n4x = MTOT*EMBED/4;
    const int n4w = EMBED*EMBED/4;

    split_x<<<(n4x+255)/256, 256>>>(x, n4x);
    split_w<<<dim3((n4w+255)/256, 4), 256>>>(Wq, Wk, Wv, Wo, n4w);
    rope_table<<<(SEQ*64)/256, 256>>>();

    gemm_mma<<<dim3(EMBED/128, MTOT/128, 3), 128, GEMM_SMEM>>>(nullptr, 0);

    attn_mma<<<dim3(SEQ/128, NHEAD, BATCH), 256, ATTN_SMEM>>>(mask);

    gemm_mma<<<dim3(EMBED/128, MTOT/128, 1), 128, GEMM_SMEM>>>(out, 3);
}